// round 7
// baseline (speedup 1.0000x reference)
#include <cuda_runtime.h>

// PixelWiseNet: out[h,w] = bias + sum_{c,k} p_a[c,k]*relu(x[c,h,w]*rowsum(M[c]) + bias_c[c] - p_t[c,k])
// C=3, H=W=1024, K=16.  Output [1024,1024] f32.
//
// PWL form per channel: g_c(u) = A[j]*u + B[j], j = #{r : st[r] <= u} (st sorted),
// A[j] = prefix-sum of sorted slopes, B[j] = suffix-sum of slope*threshold.
// u_c = x_c * sgn(scale_c); global constant folded into channel-0 B table.
//
// R6: two-level 4-ary search (register pivots -> one LDS.128 -> LDS.64),
// warp-0-only prologue with a single __syncthreads.

#define C 3
#define K 16
#define HW (1024 * 1024)
#define N4 (HW / 4)
#define THREADS 256
#define BLOCKS (N4 / THREADS)    // 1024

__global__ __launch_bounds__(THREADS, 6)
void pixelwise_kernel(const float4* __restrict__ x,
                      const float* __restrict__ M,
                      const float* __restrict__ p_a,
                      const float* __restrict__ p_t,
                      const float* __restrict__ bias_c,
                      const float* __restrict__ bias,
                      float4* __restrict__ out) {
    __shared__ __align__(16) float sh_st[C * K];   // sorted thresholds (16B aligned per channel)
    __shared__ float  sh_sa[C * K];                // slopes in sorted order
    __shared__ float  sh_tp[C * K];                // unsorted thresholds (sort scratch)
    __shared__ float  sh_ap[C * K];                // unsorted slopes
    __shared__ float2 sh_AB[C * 17];               // (A_j, B_j) per channel, 17 segments
    __shared__ float  sh_xsign[C];

    const int tid = threadIdx.x;

    // ================= prologue: warp 0 only =================
    if (tid < 32) {
        // ---- stage 1: transform params (2 hinges per lane) ----
        float cst_sum = 0.0f;
        #pragma unroll
        for (int rep = 0; rep < 2; rep++) {
            int idx = tid + rep * 32;
            if (idx < C * K) {
                int c = idx / K;
                float scale = M[c * 3 + 0] + M[c * 3 + 1] + M[c * 3 + 2];
                float sa = fabsf(scale);
                float a = p_a[idx], t = p_t[idx], bc = bias_c[c];
                float ap, tp, cst;
                if (sa > 0.0f) {
                    ap  = a * sa;
                    tp  = (t - bc) / sa;
                    cst = a * (bc - t);
                } else {
                    ap = 0.0f; tp = 0.0f;
                    cst = a * (fmaxf(bc, t) - t);
                }
                sh_tp[idx] = tp;
                sh_ap[idx] = ap;
                cst_sum += cst;
            }
        }
        if (tid < C) {
            float scale = M[tid * 3 + 0] + M[tid * 3 + 1] + M[tid * 3 + 2];
            sh_xsign[tid] = (scale >= 0.0f) ? 1.0f : -1.0f;
        }
        __syncwarp();

        // ---- CONST: warp reduction (all lanes get the sum) ----
        float cst = cst_sum;
        #pragma unroll
        for (int o = 16; o; o >>= 1) cst += __shfl_xor_sync(0xffffffffu, cst, o);
        cst += bias[0];

        // ---- stage 2: rank sort per channel ----
        #pragma unroll
        for (int rep = 0; rep < 2; rep++) {
            int idx = tid + rep * 32;
            if (idx < C * K) {
                int c = idx / K, k = idx % K;
                float my_t = sh_tp[idx];
                int rank = 0;
                #pragma unroll
                for (int j = 0; j < K; j++) {
                    float o = sh_tp[c * K + j];
                    rank += (o < my_t || (o == my_t && j < k)) ? 1 : 0;
                }
                sh_st[c * K + rank] = my_t;
                sh_sa[c * K + rank] = sh_ap[idx];
            }
        }
        __syncwarp();

        // ---- stage 3: segment tables (A_j, B_j), 51 entries ----
        #pragma unroll
        for (int rep = 0; rep < 2; rep++) {
            int e = tid + rep * 32;
            if (e < C * 17) {
                int c = e / 17, j = e % 17;
                float A = 0.0f, B = 0.0f;
                #pragma unroll
                for (int r = 0; r < K; r++) {
                    float sv = sh_sa[c * K + r];
                    if (r < j) A += sv;
                    else       B += sv * sh_st[c * K + r];
                }
                if (c == 0) B += cst;        // fold global constant into channel 0
                sh_AB[e] = make_float2(A, B);
            }
        }
    }
    __syncthreads();

    // ================= main: 4 pixels per thread =================
    const int i = blockIdx.x * THREADS + tid;

    const float xs0 = sh_xsign[0], xs1 = sh_xsign[1], xs2 = sh_xsign[2];
    const float4 v0 = x[i];
    const float4 v1 = x[N4 + i];
    const float4 v2 = x[2 * N4 + i];

    // level-1 pivots, block-uniform -> registers (broadcast LDS, once)
    float piv[C][3];
    #pragma unroll
    for (int c = 0; c < C; c++) {
        piv[c][0] = sh_st[c * K + 3];
        piv[c][1] = sh_st[c * K + 7];
        piv[c][2] = sh_st[c * K + 11];
    }
    const float4* st4 = (const float4*)sh_st;   // [C*4] quartiles

    float u[C][4];
    u[0][0] = v0.x * xs0; u[0][1] = v0.y * xs0; u[0][2] = v0.z * xs0; u[0][3] = v0.w * xs0;
    u[1][0] = v1.x * xs1; u[1][1] = v1.y * xs1; u[1][2] = v1.z * xs1; u[1][3] = v1.w * xs1;
    u[2][0] = v2.x * xs2; u[2][1] = v2.y * xs2; u[2][2] = v2.z * xs2; u[2][3] = v2.w * xs2;

    float accA[4] = {0.f, 0.f, 0.f, 0.f};
    float accB[4] = {0.f, 0.f, 0.f, 0.f};

    #pragma unroll
    for (int c = 0; c < C; c++) {
        const float p0 = piv[c][0], p1 = piv[c][1], p2 = piv[c][2];
        const float2* ab = &sh_AB[c * 17];
        #pragma unroll
        for (int p = 0; p < 4; p++) {
            float uu = u[c][p];
            // level 1: which quartile (register pivots)
            int m = (uu >= p0) + (uu >= p1) + (uu >= p2);
            // level 2: one LDS.128 of the quartile, count inside
            float4 q = st4[c * 4 + m];
            int j = m * 4 + (uu >= q.x) + (uu >= q.y) + (uu >= q.z) + (uu >= q.w);
            float2 AB = ab[j];
            accA[p] = fmaf(uu, AB.x, accA[p]);
            accB[p] += AB.y;
        }
    }

    float4 r;
    r.x = accA[0] + accB[0];
    r.y = accA[1] + accB[1];
    r.z = accA[2] + accB[2];
    r.w = accA[3] + accB[3];
    out[i] = r;
}

extern "C" void kernel_launch(void* const* d_in, const int* in_sizes, int n_in,
                              void* d_out, int out_size) {
    const float4* x      = (const float4*)d_in[0];
    const float*  M      = (const float*)d_in[1];
    const float*  p_a    = (const float*)d_in[2];
    const float*  p_t    = (const float*)d_in[3];
    const float*  bias_c = (const float*)d_in[4];
    const float*  bias   = (const float*)d_in[5];
    float4* out = (float4*)d_out;

    pixelwise_kernel<<<BLOCKS, THREADS>>>(x, M, p_a, p_t, bias_c, bias, out);
}

// round 8
// speedup vs baseline: 1.1134x; 1.1134x over previous
#include <cuda_runtime.h>

// PixelWiseNet: out[h,w] = bias + sum_{c,k} p_a[c,k]*relu(x[c,h,w]*rowsum(M[c]) + bias_c[c] - p_t[c,k])
// C=3, H=W=1024, K=16.  Output [1024,1024] f32.
//
// PWL-in-x form per channel (sign folded into tables):
//   hinge = a*relu(scale*x + bc - t) is PWL in x with breakpoint xb=(t-bc)/scale,
//   slope s=a*scale active for x>xb (scale>0) or x<xb (scale<0).
//   Sort xb; segment j = #{r: xb_r <= x}; g_c(x) = A[j]*x + B[j] with
//     scale>0: A[j]=sum_{r<j} s_r,  B[j]=-sum_{r<j} s_r*xb_r
//     scale<0: A[j]=sum_{r>=j} s_r, B[j]=-sum_{r>=j} s_r*xb_r
//   bias (+ any scale==0 constants) folded into channel-0 B.
// Hot loop per pixel-channel: 3 register-pivot compares -> 1 LDS.128 quartile
// -> 4 compares -> 1 LDS.64 (A,B) -> FFMA + FADD.

#define C 3
#define K 16
#define HW (1024 * 1024)
#define N4 (HW / 4)
#define THREADS 256
#define BLOCKS (N4 / THREADS)    // 1024

__global__ __launch_bounds__(THREADS)
void pixelwise_kernel(const float4* __restrict__ x,
                      const float* __restrict__ M,
                      const float* __restrict__ p_a,
                      const float* __restrict__ p_t,
                      const float* __restrict__ bias_c,
                      const float* __restrict__ bias,
                      float4* __restrict__ out) {
    __shared__ __align__(16) float sh_sxb[C * K];  // sorted breakpoints
    __shared__ float  sh_ss[C * K];                // slopes in sorted order
    __shared__ float  sh_xb[C * K];                // unsorted breakpoints
    __shared__ float  sh_s[C * K];                 // unsorted slopes
    __shared__ float  sh_cst[C * K];               // scale==0 constants
    __shared__ float2 sh_AB[C * 17];               // (A_j, B_j)
    __shared__ float  sh_scale[C];
    __shared__ float  sh_const;

    const int tid = threadIdx.x;

    // ---- stage 1: transform (48 lanes, warps 0-1) ----
    if (tid < C * K) {
        int c = tid / K;
        float scale = M[c * 3 + 0] + M[c * 3 + 1] + M[c * 3 + 2];
        float a = p_a[tid], t = p_t[tid], bc = bias_c[c];
        float xb, s, cst;
        if (scale != 0.0f) {
            xb  = (t - bc) / scale;
            s   = a * scale;
            cst = 0.0f;
        } else {
            xb = 0.0f; s = 0.0f;
            cst = a * fmaxf(bc - t, 0.0f);
        }
        sh_xb[tid]  = xb;
        sh_s[tid]   = s;
        sh_cst[tid] = cst;
        if (tid < C) sh_scale[tid] = scale;
    }
    __syncthreads();

    // ---- stage 2: rank sort per channel (48 lanes) + CONST (lane 48) ----
    if (tid < C * K) {
        int c = tid / K, k = tid % K;
        float my = sh_xb[tid];
        int rank = 0;
        #pragma unroll
        for (int j = 0; j < K; j++) {
            float o = sh_xb[c * K + j];
            rank += (o < my || (o == my && j < k)) ? 1 : 0;
        }
        sh_sxb[c * K + rank] = my;
        sh_ss[c * K + rank]  = sh_s[tid];
    } else if (tid == C * K) {
        float v = bias[0];
        #pragma unroll
        for (int r = 0; r < C * K; r++) v += sh_cst[r];
        sh_const = v;
    }
    __syncthreads();

    // ---- stage 3: segment tables (51 lanes) ----
    if (tid < C * 17) {
        int c = tid / 17, j = tid % 17;
        bool pos = (sh_scale[c] >= 0.0f);
        float A = 0.0f, B = 0.0f;
        #pragma unroll
        for (int r = 0; r < K; r++) {
            float sv = sh_ss[c * K + r];
            float xv = sh_sxb[c * K + r];
            bool take = pos ? (r < j) : (r >= j);
            if (take) { A += sv; B -= sv * xv; }
        }
        if (c == 0) B += sh_const;
        sh_AB[tid] = make_float2(A, B);
    }
    __syncthreads();

    // ---- main: 4 pixels per thread ----
    const int i = blockIdx.x * THREADS + tid;
    const float4 v0 = x[i];
    const float4 v1 = x[N4 + i];
    const float4 v2 = x[2 * N4 + i];

    // level-1 pivots, block-uniform broadcasts
    float pva[C], pvb[C], pvc[C];
    #pragma unroll
    for (int c = 0; c < C; c++) {
        pva[c] = sh_sxb[c * K + 3];
        pvb[c] = sh_sxb[c * K + 7];
        pvc[c] = sh_sxb[c * K + 11];
    }
    const float4* st4 = (const float4*)sh_sxb;

    float xv[C][4];
    xv[0][0] = v0.x; xv[0][1] = v0.y; xv[0][2] = v0.z; xv[0][3] = v0.w;
    xv[1][0] = v1.x; xv[1][1] = v1.y; xv[1][2] = v1.z; xv[1][3] = v1.w;
    xv[2][0] = v2.x; xv[2][1] = v2.y; xv[2][2] = v2.z; xv[2][3] = v2.w;

    float accA[4] = {0.f, 0.f, 0.f, 0.f};
    float accB[4] = {0.f, 0.f, 0.f, 0.f};

    #pragma unroll
    for (int c = 0; c < C; c++) {
        const float p0 = pva[c], p1 = pvb[c], p2 = pvc[c];
        const float2* ab = &sh_AB[c * 17];

        // batch: 4 independent m's, then 4 LDS.128, then 4 j's, then 4 LDS.64
        int m0 = (xv[c][0] >= p0) + (xv[c][0] >= p1) + (xv[c][0] >= p2);
        int m1 = (xv[c][1] >= p0) + (xv[c][1] >= p1) + (xv[c][1] >= p2);
        int m2 = (xv[c][2] >= p0) + (xv[c][2] >= p1) + (xv[c][2] >= p2);
        int m3 = (xv[c][3] >= p0) + (xv[c][3] >= p1) + (xv[c][3] >= p2);

        float4 q0 = st4[c * 4 + m0];
        float4 q1 = st4[c * 4 + m1];
        float4 q2 = st4[c * 4 + m2];
        float4 q3 = st4[c * 4 + m3];

        int j0 = m0 * 4 + (xv[c][0] >= q0.x) + (xv[c][0] >= q0.y) + (xv[c][0] >= q0.z) + (xv[c][0] >= q0.w);
        int j1 = m1 * 4 + (xv[c][1] >= q1.x) + (xv[c][1] >= q1.y) + (xv[c][1] >= q1.z) + (xv[c][1] >= q1.w);
        int j2 = m2 * 4 + (xv[c][2] >= q2.x) + (xv[c][2] >= q2.y) + (xv[c][2] >= q2.z) + (xv[c][2] >= q2.w);
        int j3 = m3 * 4 + (xv[c][3] >= q3.x) + (xv[c][3] >= q3.y) + (xv[c][3] >= q3.z) + (xv[c][3] >= q3.w);

        float2 ab0 = ab[j0];
        float2 ab1 = ab[j1];
        float2 ab2 = ab[j2];
        float2 ab3 = ab[j3];

        accA[0] = fmaf(xv[c][0], ab0.x, accA[0]);  accB[0] += ab0.y;
        accA[1] = fmaf(xv[c][1], ab1.x, accA[1]);  accB[1] += ab1.y;
        accA[2] = fmaf(xv[c][2], ab2.x, accA[2]);  accB[2] += ab2.y;
        accA[3] = fmaf(xv[c][3], ab3.x, accA[3]);  accB[3] += ab3.y;
    }

    float4 r;
    r.x = accA[0] + accB[0];
    r.y = accA[1] + accB[1];
    r.z = accA[2] + accB[2];
    r.w = accA[3] + accB[3];
    out[i] = r;
}

extern "C" void kernel_launch(void* const* d_in, const int* in_sizes, int n_in,
                              void* d_out, int out_size) {
    const float4* x      = (const float4*)d_in[0];
    const float*  M      = (const float*)d_in[1];
    const float*  p_a    = (const float*)d_in[2];
    const float*  p_t    = (const float*)d_in[3];
    const float*  bias_c = (const float*)d_in[4];
    const float*  bias   = (const float*)d_in[5];
    float4* out = (float4*)d_out;

    pixelwise_kernel<<<BLOCKS, THREADS>>>(x, M, p_a, p_t, bias_c, bias, out);
}